// round 13
// baseline (speedup 1.0000x reference)
#include <cuda_runtime.h>
#include <cuda_bf16.h>
#include <math.h>
#include <stdint.h>

#define D_DIM  1024
#define C_CLS  1000
#define B_ROWS 4096
#define M_ROWS 32768
#define MAXR   (B_ROWS + M_ROWS)   // 36864 max enhanced unique rows
#define TEMP_INV 10.0f
#define EPSF 1e-8f
#define HARD_K 10

typedef unsigned long long ull;

// ---------------- device scratch ----------------
__device__ __nv_bfloat16 g_A16[(size_t)MAXR * D_DIM];   // 75.5 MB (rows: z_img | memF)
__device__ __nv_bfloat16 g_B16[(size_t)1024 * D_DIM];   // 2 MB (z_prompts, zero-padded)
__device__ float g_sim[(size_t)MAXR * C_CLS];           // 147 MB
__device__ float g_w[1024];                             // padded (only [0,1000) meaningful)
__device__ int   g_pcounts[32][C_CLS];                  // per-rowblock partial counts
__device__ double g_loss;
__device__ double g_nvalid;

#define NEG_INF (__int_as_float(0xff800000))

// ---------------- PTX helpers (sm_80+ ISA only; no tcgen05) ----------------
__device__ __forceinline__ uint32_t smem_to_u32(const void* p) {
    uint32_t a;
    asm("{ .reg .u64 t; cvta.to.shared.u64 t, %1; cvt.u32.u64 %0, t; }" : "=r"(a) : "l"(p));
    return a;
}
__device__ __forceinline__ void cp16(uint32_t s, const void* g) {
    asm volatile("cp.async.cg.shared.global [%0], [%1], 16;" :: "r"(s), "l"(g) : "memory");
}
#define CP_COMMIT() asm volatile("cp.async.commit_group;" ::: "memory")
#define CP_WAIT1()  asm volatile("cp.async.wait_group 1;" ::: "memory")

#define LDSM4(r, addr) \
    asm volatile("ldmatrix.sync.aligned.m8n8.x4.shared.b16 {%0,%1,%2,%3}, [%4];" \
        : "=r"((r)[0]), "=r"((r)[1]), "=r"((r)[2]), "=r"((r)[3]) : "r"(addr))

#define MMA16816(c, a, b0, b1) \
    asm volatile("mma.sync.aligned.m16n8k16.row.col.f32.bf16.bf16.f32 " \
        "{%0,%1,%2,%3}, {%4,%5,%6,%7}, {%8,%9}, {%0,%1,%2,%3};" \
        : "+f"((c)[0]), "+f"((c)[1]), "+f"((c)[2]), "+f"((c)[3]) \
        : "r"((a)[0]), "r"((a)[1]), "r"((a)[2]), "r"((a)[3]), "r"(b0), "r"(b1))

// ---------------- block reductions ----------------
__device__ __forceinline__ float blockReduceSumF(float v, float* sred) {
    int lane = threadIdx.x & 31, wid = threadIdx.x >> 5;
    int nw = blockDim.x >> 5;
    #pragma unroll
    for (int o = 16; o; o >>= 1) v += __shfl_xor_sync(0xffffffffu, v, o);
    if (lane == 0) sred[wid] = v;
    __syncthreads();
    if (wid == 0) {
        v = (lane < nw) ? sred[lane] : 0.0f;
        #pragma unroll
        for (int o = 16; o; o >>= 1) v += __shfl_xor_sync(0xffffffffu, v, o);
        if (lane == 0) sred[0] = v;
    }
    __syncthreads();
    v = sred[0];
    __syncthreads();
    return v;
}

// ---------------- fused staging: norm_img | norm_prompts | conv_mem(x4) | counts ----------------
#define MEM_BLKS         (M_ROWS / 4)
#define STAGE_IMG_END    (B_ROWS)
#define STAGE_PRM_END    (B_ROWS + 1024)
#define STAGE_MEM_END    (B_ROWS + 1024 + MEM_BLKS)
#define STAGE_GRID       (STAGE_MEM_END + 128)

__global__ void __launch_bounds__(256) stage_kernel(const float* __restrict__ img,
                                                    const float* __restrict__ prompts,
                                                    const float* __restrict__ memF,
                                                    const int* __restrict__ labels,
                                                    const int* __restrict__ memptr_p) {
    int b = blockIdx.x;
    int t = threadIdx.x;

    if (b < STAGE_IMG_END) {                       // normalize images -> g_A16[0, B)
        __shared__ float sred[32];
        const float4* src = (const float4*)(img + (size_t)b * D_DIM);
        float4 v = src[t];
        float ss = v.x * v.x + v.y * v.y + v.z * v.z + v.w * v.w;
        ss = blockReduceSumF(ss, sred);
        float inv = rsqrtf(ss + 1e-24f);
        __nv_bfloat162 lo = __floats2bfloat162_rn(v.x * inv, v.y * inv);
        __nv_bfloat162 hi = __floats2bfloat162_rn(v.z * inv, v.w * inv);
        ((uint2*)(g_A16 + (size_t)b * D_DIM))[t] = make_uint2(*(uint32_t*)&lo, *(uint32_t*)&hi);
    } else if (b < STAGE_PRM_END) {                // normalize prompts -> g_B16 (zero-pad >= C)
        int r = b - STAGE_IMG_END;
        uint2* dst = (uint2*)(g_B16 + (size_t)r * D_DIM);
        if (r >= C_CLS) { dst[t] = make_uint2(0u, 0u); return; }
        __shared__ float sred[32];
        const float4* src = (const float4*)(prompts + (size_t)r * D_DIM);
        float4 v = src[t];
        float ss = v.x * v.x + v.y * v.y + v.z * v.z + v.w * v.w;
        ss = blockReduceSumF(ss, sred);
        float inv = rsqrtf(ss + 1e-24f);
        __nv_bfloat162 lo = __floats2bfloat162_rn(v.x * inv, v.y * inv);
        __nv_bfloat162 hi = __floats2bfloat162_rn(v.z * inv, v.w * inv);
        dst[t] = make_uint2(*(uint32_t*)&lo, *(uint32_t*)&hi);
    } else if (b < STAGE_MEM_END) {                // memF fp32->bf16, 4 rows/block (MLP=4)
        int rblk = b - STAGE_PRM_END;
        int mp = memptr_p[0];
        int base = rblk * 4;
        if (base >= mp) return;
        float4 v[4];
        #pragma unroll
        for (int j = 0; j < 4; j++) {
            int r = base + j;
            if (r < mp) v[j] = ((const float4*)(memF + (size_t)r * D_DIM))[t];
        }
        #pragma unroll
        for (int j = 0; j < 4; j++) {
            int r = base + j;
            if (r < mp) {
                __nv_bfloat162 lo = __floats2bfloat162_rn(v[j].x, v[j].y);
                __nv_bfloat162 hi = __floats2bfloat162_rn(v[j].z, v[j].w);
                ((uint2*)(g_A16 + (size_t)(B_ROWS + r) * D_DIM))[t] =
                    make_uint2(*(uint32_t*)&lo, *(uint32_t*)&hi);
            }
        }
    } else {                                       // partial class counts (128 blocks, no atomics)
        int g = b - STAGE_MEM_END;                 // (cblk 0..3, rblk 0..31)
        int c = (g & 3) * 256 + t;
        if (c >= C_CLS) return;
        int rblk = g >> 2;
        const int* p = labels + (size_t)(rblk * 128) * C_CLS + c;
        int s = 0;
        #pragma unroll 8
        for (int i = 0; i < 128; i++) s += p[(size_t)i * C_CLS];
        g_pcounts[rblk][c] = s;
    }
}

// weights + zero loss accumulators
__global__ void weights_kernel() {
    __shared__ float sred[32];
    int c = threadIdx.x;
    if (c == 0) { g_loss = 0.0; g_nvalid = 0.0; }
    float w = 0.0f;
    if (c < C_CLS) {
        int cnt = 0;
        #pragma unroll
        for (int j = 0; j < 32; j++) cnt += g_pcounts[j][c];
        float eff = 1.0f - powf(0.999f, (float)cnt);
        w = (1.0f - 0.999f) / (eff + EPSF);
    }
    float tot = blockReduceSumF(w, sred);
    if (c < C_CLS) g_w[c] = w / tot * (float)C_CLS;
}

// ---------------- bf16 mma.sync GEMM: sim = A16 @ B16^T * 10 (R10 config, unchanged) ----------------
#define GS_A      16384u                    // 128 rows * 128 B
#define GS_B      16384u                    // 128 rows * 128 B
#define GS_STAGE  (GS_A + GS_B)             // 32 KB
#define GSM_DYN   (3 * GS_STAGE + 128)      // ~96 KB

__global__ void __launch_bounds__(256, 2) gemm_mma_kernel(const int* __restrict__ memptr_p) {
    int rowsEff = B_ROWS + memptr_p[0];
    int rowBase = blockIdx.y * 128;
    if (rowBase >= rowsEff) return;
    int colBase = blockIdx.x * 128;

    extern __shared__ char dynsm[];
    uint32_t sbase = (smem_to_u32(dynsm) + 127u) & ~127u;

    int tid = threadIdx.x;
    int warp = tid >> 5, lane = tid & 31;
    int lrow = tid >> 1, lhalf = tid & 1;   // loader: half-row (64B) per thread

    const char* aG = (const char*)(g_A16 + (size_t)(rowBase + lrow) * D_DIM) + lhalf * 64;
    const char* bG = (const char*)(g_B16 + (size_t)(colBase + lrow) * D_DIM) + lhalf * 64;
    uint32_t soA[4];
    #pragma unroll
    for (int j = 0; j < 4; j++) {
        uint32_t o0 = (uint32_t)lrow * 128u + (uint32_t)lhalf * 64u + j * 16u;
        soA[j] = o0 ^ ((o0 >> 3) & 0x70u);
    }

#define G_ISSUE(kt, s) do { \
        uint32_t as_ = sbase + (uint32_t)(s) * GS_STAGE; \
        uint32_t bs_ = as_ + GS_A; \
        const char* ag_ = aG + (size_t)(kt) * 128; \
        const char* bg_ = bG + (size_t)(kt) * 128; \
        _Pragma("unroll") \
        for (int j_ = 0; j_ < 4; j_++) { \
            cp16(as_ + soA[j_], ag_ + j_ * 16); \
            cp16(bs_ + soA[j_], bg_ + j_ * 16); \
        } \
    } while (0)

    float acc[2][8][4];
    #pragma unroll
    for (int mt = 0; mt < 2; mt++)
        #pragma unroll
        for (int nt = 0; nt < 8; nt++)
            #pragma unroll
            for (int q = 0; q < 4; q++) acc[mt][nt][q] = 0.0f;

    const int NT = D_DIM / 64;   // 16 k-tiles
    G_ISSUE(0, 0); CP_COMMIT();
    G_ISSUE(1, 1); CP_COMMIT();

    int m0 = (warp & 3) * 32, n0 = (warp >> 2) * 64;
    int flr = lane & 15;
    int fkh = (lane >> 4) * 16;

    int s = 0;           // slot of stage kt
    int sNext = 2;       // slot of stage kt+2
    for (int kt = 0; kt < NT; kt++) {
        uint32_t as_ = sbase + (uint32_t)s * GS_STAGE;
        uint32_t bs_ = as_ + GS_A;
        CP_WAIT1();
        __syncthreads();

        if (kt + 2 < NT) {
            G_ISSUE(kt + 2, sNext);
            CP_COMMIT();
        }

        #pragma unroll
        for (int ks = 0; ks < 4; ks++) {
            uint32_t kb = (uint32_t)(ks * 32 + fkh);
            uint32_t afr[2][4];
            #pragma unroll
            for (int mt = 0; mt < 2; mt++) {
                uint32_t off = (uint32_t)(m0 + mt * 16 + flr) * 128u + kb;
                LDSM4(afr[mt], as_ + (off ^ ((off >> 3) & 0x70u)));
            }
            uint32_t bfr[4][4];
            #pragma unroll
            for (int p = 0; p < 4; p++) {
                uint32_t off = (uint32_t)(n0 + p * 16 + flr) * 128u + kb;
                LDSM4(bfr[p], bs_ + (off ^ ((off >> 3) & 0x70u)));
            }
            #pragma unroll
            for (int mt = 0; mt < 2; mt++)
                #pragma unroll
                for (int nt = 0; nt < 8; nt++) {
                    int p = nt >> 1, w = nt & 1;
                    MMA16816(acc[mt][nt], afr[mt], bfr[p][w], bfr[p][w + 2]);
                }
        }
        s = (s == 2) ? 0 : s + 1;
        sNext = (sNext == 2) ? 0 : sNext + 1;
    }

    // store C * 10
    int mrow = lane >> 2;
    int ncol = (lane & 3) * 2;
    #pragma unroll
    for (int mt = 0; mt < 2; mt++)
        #pragma unroll
        for (int h = 0; h < 2; h++) {
            int r = rowBase + m0 + mt * 16 + h * 8 + mrow;
            if (r < rowsEff) {
                float* dst = g_sim + (size_t)r * C_CLS;
                #pragma unroll
                for (int nt = 0; nt < 8; nt++) {
                    int c = colBase + n0 + nt * 8 + ncol;
                    float v0 = acc[mt][nt][h * 2 + 0] * TEMP_INV;
                    float v1 = acc[mt][nt][h * 2 + 1] * TEMP_INV;
                    if (c + 1 < C_CLS) {
                        *(float2*)(dst + c) = make_float2(v0, v1);
                    } else if (c < C_CLS) {
                        dst[c] = v0;
                    }
                }
            }
        }
#undef G_ISSUE
}

// ---------------- epilogue: warp-per-row, 2-pass (L2-hot re-read), low-reg for occupancy ----------------
// Lane owns float4 chunks k = i*32+lane (i=0..7); class c = 4k+j. 250 float4 = 1000 floats.
__global__ void __launch_bounds__(256) epilogue_kernel(const int* __restrict__ labels,
                                                       const int* __restrict__ memL,
                                                       const int* __restrict__ memptr_p) {
    int mp = memptr_p[0];
    int rowsEff = B_ROWS + mp;
    int wid = threadIdx.x >> 5, lane = threadIdx.x & 31;
    int r = blockIdx.x * 8 + wid;
    bool active = (r < rowsEff);

    __shared__ double s_bl, s_bn;
    if (threadIdx.x == 0) { s_bl = 0.0; s_bn = 0.0; }
    __syncthreads();

    if (active) {
        const int* labRow = (r < B_ROWS) ? (labels + (size_t)r * C_CLS)
                                         : (memL + (size_t)(r - B_ROWS) * C_CLS);
        float wfac = (r < B_ROWS) ? 2.0f : 1.0f;   // z_img rows duplicated in enhanced set
        const float4* s4 = (const float4*)(g_sim + (size_t)r * C_CLS);
        const int4*   l4 = (const int4*)labRow;

        float t[HARD_K];
        #pragma unroll
        for (int j = 0; j < HARD_K; j++) t[j] = NEG_INF;
        float maxpos = NEG_INF;

        // pass 1: top-10 of negatives + max positive (no value caching -> low regs)
        #pragma unroll
        for (int i = 0; i < 8; i++) {
            int k = i * 32 + lane;
            bool okv = (k < 250);
            int kc = okv ? k : 249;               // clamp (no OOB); masked below
            float4 v4 = s4[kc];
            int4   b4 = l4[kc];
            if (!okv) {
                v4.x = v4.y = v4.z = v4.w = NEG_INF;
                b4.x = b4.y = b4.z = b4.w = 0;
            }
            float vv[4] = {v4.x, v4.y, v4.z, v4.w};
            int   ll[4] = {b4.x, b4.y, b4.z, b4.w};
            #pragma unroll
            for (int j = 0; j < 4; j++) {
                float v = vv[j];
                if (ll[j] > 0) {
                    maxpos = fmaxf(maxpos, v);
                } else if (v > t[HARD_K - 1]) {
                    t[HARD_K - 1] = v;
                    #pragma unroll
                    for (int q = HARD_K - 1; q > 0; q--) {
                        if (t[q] > t[q - 1]) { float tm = t[q - 1]; t[q - 1] = t[q]; t[q] = tm; }
                    }
                }
            }
        }

        // merge: exact 10th-largest negative across the warp (with multiplicity)
        float thr = NEG_INF, top1 = NEG_INF;
        for (int it = 0; it < HARD_K; it++) {
            float mx = t[0];
            #pragma unroll
            for (int o = 16; o; o >>= 1) mx = fmaxf(mx, __shfl_xor_sync(0xffffffffu, mx, o));
            if (it == 0) top1 = mx;
            if (it == HARD_K - 1) { thr = mx; break; }
            unsigned ball = __ballot_sync(0xffffffffu, t[0] == mx);
            int owner = __ffs(ball) - 1;
            if (lane == owner) {   // pop head
                #pragma unroll
                for (int j = 0; j < HARD_K - 1; j++) t[j] = t[j + 1];
                t[HARD_K - 1] = NEG_INF;
            }
        }

        float mp2 = maxpos;
        #pragma unroll
        for (int o = 16; o; o >>= 1) mp2 = fmaxf(mp2, __shfl_xor_sync(0xffffffffu, mp2, o));
        float mx = fmaxf(mp2, top1);

        // pass 2: re-read (L2-hot) -> masked sumexp + weighted sums
        float se = 0.0f, ws = 0.0f, wv = 0.0f;
        #pragma unroll
        for (int i = 0; i < 8; i++) {
            int k = i * 32 + lane;
            bool okv = (k < 250);
            int kc = okv ? k : 249;
            float4 v4 = s4[kc];
            int4   b4 = l4[kc];
            if (!okv) {
                v4.x = v4.y = v4.z = v4.w = NEG_INF;
                b4.x = b4.y = b4.z = b4.w = 0;
            }
            float vv[4] = {v4.x, v4.y, v4.z, v4.w};
            int   ll[4] = {b4.x, b4.y, b4.z, b4.w};
            #pragma unroll
            for (int j = 0; j < 4; j++) {
                float v = vv[j];
                bool p = (ll[j] > 0);
                if (p || v >= thr) se += expf(v - mx);
                if (p) {
                    float w = g_w[i * 128 + lane * 4 + j];
                    ws += w;
                    wv += w * v;
                }
            }
        }
        #pragma unroll
        for (int o = 16; o; o >>= 1) {
            se += __shfl_xor_sync(0xffffffffu, se, o);
            ws += __shfl_xor_sync(0xffffffffu, ws, o);
            wv += __shfl_xor_sync(0xffffffffu, wv, o);
        }

        if (lane == 0 && ws > 0.0f) {
            float lse = mx + logf(se);
            atomicAdd(&s_bl, (double)(wfac * ((lse * ws - wv) / (ws + EPSF))));
            atomicAdd(&s_bn, (double)wfac);
        }
    }

    __syncthreads();
    if (threadIdx.x == 0 && s_bn != 0.0) {
        atomicAdd(&g_loss, s_bl);
        atomicAdd(&g_nvalid, s_bn);
    }
}

__global__ void finalize_kernel(float* __restrict__ out) {
    double nv = g_nvalid;
    if (nv < 1.0) nv = 1.0;
    out[0] = (float)(g_loss / nv);
}

// ---------------- launch ----------------
extern "C" void kernel_launch(void* const* d_in, const int* in_sizes, int n_in,
                              void* d_out, int out_size) {
    const float* img     = (const float*)d_in[0];
    const float* prompts = (const float*)d_in[1];
    const int*   labels  = (const int*)d_in[2];
    const float* memF    = (const float*)d_in[3];
    const int*   memL    = (const int*)d_in[4];
    const int*   memptr  = (const int*)d_in[5];
    float* out = (float*)d_out;
    (void)in_sizes; (void)n_in; (void)out_size;

    cudaFuncSetAttribute(gemm_mma_kernel, cudaFuncAttributeMaxDynamicSharedMemorySize, GSM_DYN);

    stage_kernel<<<STAGE_GRID, 256>>>(img, prompts, memF, labels, memptr);
    weights_kernel<<<1, 1024>>>();
    gemm_mma_kernel<<<dim3(8, MAXR / 128), 256, GSM_DYN>>>(memptr);
    epilogue_kernel<<<(MAXR + 7) / 8, 256>>>(labels, memL, memptr);
    finalize_kernel<<<1, 1>>>(out);
}

// round 16
// speedup vs baseline: 1.1425x; 1.1425x over previous
#include <cuda_runtime.h>
#include <cuda_bf16.h>
#include <math.h>
#include <stdint.h>

#define D_DIM  1024
#define C_CLS  1000
#define B_ROWS 4096
#define M_ROWS 32768
#define MAXR   (B_ROWS + M_ROWS)   // 36864 max enhanced unique rows
#define TEMP_INV 10.0f
#define EPSF 1e-8f
#define HARD_K 10

typedef unsigned long long ull;

// ---------------- device scratch ----------------
__device__ __nv_bfloat16 g_A16[(size_t)MAXR * D_DIM];   // 75.5 MB (rows: z_img | memF)
__device__ __nv_bfloat16 g_B16[(size_t)1024 * D_DIM];   // 2 MB (z_prompts, zero-padded)
__device__ float g_sim[(size_t)MAXR * C_CLS];           // 147 MB
__device__ float g_w[1024];                             // padded (only [0,1000) meaningful)
__device__ int   g_pcounts[32][C_CLS];                  // per-rowblock partial counts
__device__ double g_loss;
__device__ double g_nvalid;

#define NEG_INF (__int_as_float(0xff800000))

// ---------------- PTX helpers (sm_80+ ISA only; no tcgen05) ----------------
__device__ __forceinline__ uint32_t smem_to_u32(const void* p) {
    uint32_t a;
    asm("{ .reg .u64 t; cvta.to.shared.u64 t, %1; cvt.u32.u64 %0, t; }" : "=r"(a) : "l"(p));
    return a;
}
__device__ __forceinline__ void cp16(uint32_t s, const void* g) {
    asm volatile("cp.async.cg.shared.global [%0], [%1], 16;" :: "r"(s), "l"(g) : "memory");
}
#define CP_COMMIT() asm volatile("cp.async.commit_group;" ::: "memory")
#define CP_WAIT1()  asm volatile("cp.async.wait_group 1;" ::: "memory")

#define LDSM4(r, addr) \
    asm volatile("ldmatrix.sync.aligned.m8n8.x4.shared.b16 {%0,%1,%2,%3}, [%4];" \
        : "=r"((r)[0]), "=r"((r)[1]), "=r"((r)[2]), "=r"((r)[3]) : "r"(addr))

#define MMA16816(c, a, b0, b1) \
    asm volatile("mma.sync.aligned.m16n8k16.row.col.f32.bf16.bf16.f32 " \
        "{%0,%1,%2,%3}, {%4,%5,%6,%7}, {%8,%9}, {%0,%1,%2,%3};" \
        : "+f"((c)[0]), "+f"((c)[1]), "+f"((c)[2]), "+f"((c)[3]) \
        : "r"((a)[0]), "r"((a)[1]), "r"((a)[2]), "r"((a)[3]), "r"(b0), "r"(b1))

// ---------------- block reductions ----------------
__device__ __forceinline__ float blockReduceSumF(float v, float* sred) {
    int lane = threadIdx.x & 31, wid = threadIdx.x >> 5;
    int nw = blockDim.x >> 5;
    #pragma unroll
    for (int o = 16; o; o >>= 1) v += __shfl_xor_sync(0xffffffffu, v, o);
    if (lane == 0) sred[wid] = v;
    __syncthreads();
    if (wid == 0) {
        v = (lane < nw) ? sred[lane] : 0.0f;
        #pragma unroll
        for (int o = 16; o; o >>= 1) v += __shfl_xor_sync(0xffffffffu, v, o);
        if (lane == 0) sred[0] = v;
    }
    __syncthreads();
    v = sred[0];
    __syncthreads();
    return v;
}

// ---------------- fused staging: norm_img | norm_prompts | conv_mem(x4) | counts ----------------
#define MEM_BLKS         (M_ROWS / 4)
#define STAGE_IMG_END    (B_ROWS)
#define STAGE_PRM_END    (B_ROWS + 1024)
#define STAGE_MEM_END    (B_ROWS + 1024 + MEM_BLKS)
#define STAGE_GRID       (STAGE_MEM_END + 128)

__global__ void __launch_bounds__(256) stage_kernel(const float* __restrict__ img,
                                                    const float* __restrict__ prompts,
                                                    const float* __restrict__ memF,
                                                    const int* __restrict__ labels,
                                                    const int* __restrict__ memptr_p) {
    int b = blockIdx.x;
    int t = threadIdx.x;

    if (b < STAGE_IMG_END) {                       // normalize images -> g_A16[0, B)
        __shared__ float sred[32];
        const float4* src = (const float4*)(img + (size_t)b * D_DIM);
        float4 v = src[t];
        float ss = v.x * v.x + v.y * v.y + v.z * v.z + v.w * v.w;
        ss = blockReduceSumF(ss, sred);
        float inv = rsqrtf(ss + 1e-24f);
        __nv_bfloat162 lo = __floats2bfloat162_rn(v.x * inv, v.y * inv);
        __nv_bfloat162 hi = __floats2bfloat162_rn(v.z * inv, v.w * inv);
        ((uint2*)(g_A16 + (size_t)b * D_DIM))[t] = make_uint2(*(uint32_t*)&lo, *(uint32_t*)&hi);
    } else if (b < STAGE_PRM_END) {                // normalize prompts -> g_B16 (zero-pad >= C)
        int r = b - STAGE_IMG_END;
        uint2* dst = (uint2*)(g_B16 + (size_t)r * D_DIM);
        if (r >= C_CLS) { dst[t] = make_uint2(0u, 0u); return; }
        __shared__ float sred[32];
        const float4* src = (const float4*)(prompts + (size_t)r * D_DIM);
        float4 v = src[t];
        float ss = v.x * v.x + v.y * v.y + v.z * v.z + v.w * v.w;
        ss = blockReduceSumF(ss, sred);
        float inv = rsqrtf(ss + 1e-24f);
        __nv_bfloat162 lo = __floats2bfloat162_rn(v.x * inv, v.y * inv);
        __nv_bfloat162 hi = __floats2bfloat162_rn(v.z * inv, v.w * inv);
        dst[t] = make_uint2(*(uint32_t*)&lo, *(uint32_t*)&hi);
    } else if (b < STAGE_MEM_END) {                // memF fp32->bf16, 4 rows/block (MLP=4)
        int rblk = b - STAGE_PRM_END;
        int mp = memptr_p[0];
        int base = rblk * 4;
        if (base >= mp) return;
        float4 v[4];
        #pragma unroll
        for (int j = 0; j < 4; j++) {
            int r = base + j;
            if (r < mp) v[j] = ((const float4*)(memF + (size_t)r * D_DIM))[t];
        }
        #pragma unroll
        for (int j = 0; j < 4; j++) {
            int r = base + j;
            if (r < mp) {
                __nv_bfloat162 lo = __floats2bfloat162_rn(v[j].x, v[j].y);
                __nv_bfloat162 hi = __floats2bfloat162_rn(v[j].z, v[j].w);
                ((uint2*)(g_A16 + (size_t)(B_ROWS + r) * D_DIM))[t] =
                    make_uint2(*(uint32_t*)&lo, *(uint32_t*)&hi);
            }
        }
    } else {                                       // partial class counts (128 blocks, no atomics)
        int g = b - STAGE_MEM_END;                 // (cblk 0..3, rblk 0..31)
        int c = (g & 3) * 256 + t;
        if (c >= C_CLS) return;
        int rblk = g >> 2;
        const int* p = labels + (size_t)(rblk * 128) * C_CLS + c;
        int s = 0;
        #pragma unroll 8
        for (int i = 0; i < 128; i++) s += p[(size_t)i * C_CLS];
        g_pcounts[rblk][c] = s;
    }
}

// weights + zero loss accumulators
__global__ void weights_kernel() {
    __shared__ float sred[32];
    int c = threadIdx.x;
    if (c == 0) { g_loss = 0.0; g_nvalid = 0.0; }
    float w = 0.0f;
    if (c < C_CLS) {
        int cnt = 0;
        #pragma unroll
        for (int j = 0; j < 32; j++) cnt += g_pcounts[j][c];
        float eff = 1.0f - powf(0.999f, (float)cnt);
        w = (1.0f - 0.999f) / (eff + EPSF);
    }
    float tot = blockReduceSumF(w, sred);
    if (c < C_CLS) g_w[c] = w / tot * (float)C_CLS;
}

// ---------------- bf16 mma.sync GEMM: sim = A16 @ B16^T * 10 (R10 config, unchanged) ----------------
#define GS_A      16384u                    // 128 rows * 128 B
#define GS_B      16384u                    // 128 rows * 128 B
#define GS_STAGE  (GS_A + GS_B)             // 32 KB
#define GSM_DYN   (3 * GS_STAGE + 128)      // ~96 KB

__global__ void __launch_bounds__(256, 2) gemm_mma_kernel(const int* __restrict__ memptr_p) {
    int rowsEff = B_ROWS + memptr_p[0];
    int rowBase = blockIdx.y * 128;
    if (rowBase >= rowsEff) return;
    int colBase = blockIdx.x * 128;

    extern __shared__ char dynsm[];
    uint32_t sbase = (smem_to_u32(dynsm) + 127u) & ~127u;

    int tid = threadIdx.x;
    int warp = tid >> 5, lane = tid & 31;
    int lrow = tid >> 1, lhalf = tid & 1;   // loader: half-row (64B) per thread

    const char* aG = (const char*)(g_A16 + (size_t)(rowBase + lrow) * D_DIM) + lhalf * 64;
    const char* bG = (const char*)(g_B16 + (size_t)(colBase + lrow) * D_DIM) + lhalf * 64;
    uint32_t soA[4];
    #pragma unroll
    for (int j = 0; j < 4; j++) {
        uint32_t o0 = (uint32_t)lrow * 128u + (uint32_t)lhalf * 64u + j * 16u;
        soA[j] = o0 ^ ((o0 >> 3) & 0x70u);
    }

#define G_ISSUE(kt, s) do { \
        uint32_t as_ = sbase + (uint32_t)(s) * GS_STAGE; \
        uint32_t bs_ = as_ + GS_A; \
        const char* ag_ = aG + (size_t)(kt) * 128; \
        const char* bg_ = bG + (size_t)(kt) * 128; \
        _Pragma("unroll") \
        for (int j_ = 0; j_ < 4; j_++) { \
            cp16(as_ + soA[j_], ag_ + j_ * 16); \
            cp16(bs_ + soA[j_], bg_ + j_ * 16); \
        } \
    } while (0)

    float acc[2][8][4];
    #pragma unroll
    for (int mt = 0; mt < 2; mt++)
        #pragma unroll
        for (int nt = 0; nt < 8; nt++)
            #pragma unroll
            for (int q = 0; q < 4; q++) acc[mt][nt][q] = 0.0f;

    const int NT = D_DIM / 64;   // 16 k-tiles
    G_ISSUE(0, 0); CP_COMMIT();
    G_ISSUE(1, 1); CP_COMMIT();

    int m0 = (warp & 3) * 32, n0 = (warp >> 2) * 64;
    int flr = lane & 15;
    int fkh = (lane >> 4) * 16;

    int s = 0;           // slot of stage kt
    int sNext = 2;       // slot of stage kt+2
    for (int kt = 0; kt < NT; kt++) {
        uint32_t as_ = sbase + (uint32_t)s * GS_STAGE;
        uint32_t bs_ = as_ + GS_A;
        CP_WAIT1();
        __syncthreads();

        if (kt + 2 < NT) {
            G_ISSUE(kt + 2, sNext);
            CP_COMMIT();
        }

        #pragma unroll
        for (int ks = 0; ks < 4; ks++) {
            uint32_t kb = (uint32_t)(ks * 32 + fkh);
            uint32_t afr[2][4];
            #pragma unroll
            for (int mt = 0; mt < 2; mt++) {
                uint32_t off = (uint32_t)(m0 + mt * 16 + flr) * 128u + kb;
                LDSM4(afr[mt], as_ + (off ^ ((off >> 3) & 0x70u)));
            }
            uint32_t bfr[4][4];
            #pragma unroll
            for (int p = 0; p < 4; p++) {
                uint32_t off = (uint32_t)(n0 + p * 16 + flr) * 128u + kb;
                LDSM4(bfr[p], bs_ + (off ^ ((off >> 3) & 0x70u)));
            }
            #pragma unroll
            for (int mt = 0; mt < 2; mt++)
                #pragma unroll
                for (int nt = 0; nt < 8; nt++) {
                    int p = nt >> 1, w = nt & 1;
                    MMA16816(acc[mt][nt], afr[mt], bfr[p][w], bfr[p][w + 2]);
                }
        }
        s = (s == 2) ? 0 : s + 1;
        sNext = (sNext == 2) ? 0 : sNext + 1;
    }

    // store C * 10
    int mrow = lane >> 2;
    int ncol = (lane & 3) * 2;
    #pragma unroll
    for (int mt = 0; mt < 2; mt++)
        #pragma unroll
        for (int h = 0; h < 2; h++) {
            int r = rowBase + m0 + mt * 16 + h * 8 + mrow;
            if (r < rowsEff) {
                float* dst = g_sim + (size_t)r * C_CLS;
                #pragma unroll
                for (int nt = 0; nt < 8; nt++) {
                    int c = colBase + n0 + nt * 8 + ncol;
                    float v0 = acc[mt][nt][h * 2 + 0] * TEMP_INV;
                    float v1 = acc[mt][nt][h * 2 + 1] * TEMP_INV;
                    if (c + 1 < C_CLS) {
                        *(float2*)(dst + c) = make_float2(v0, v1);
                    } else if (c < C_CLS) {
                        dst[c] = v0;
                    }
                }
            }
        }
#undef G_ISSUE
}

// ---------------- epilogue: warp-per-row, SMEM row cache (low regs -> high occ) ----------------
// Lane owns float4 chunks k = i*32+lane (i=0..7); class c = 4k+j. 250 float4 = 1000 floats.
// Pass 1: single global read -> smem cache + posm bitmask + per-lane top-10 of negatives.
// Pass 2: re-read from SMEM (no second global sweep).
__global__ void __launch_bounds__(256) epilogue_kernel(const int* __restrict__ labels,
                                                       const int* __restrict__ memL,
                                                       const int* __restrict__ memptr_p) {
    int mp = memptr_p[0];
    int rowsEff = B_ROWS + mp;
    int wid = threadIdx.x >> 5, lane = threadIdx.x & 31;
    int r = blockIdx.x * 8 + wid;
    bool active = (r < rowsEff);

    __shared__ float4 s_val[8][250];   // 32000 B row cache (per-warp)
    __shared__ double s_bl, s_bn;
    if (threadIdx.x == 0) { s_bl = 0.0; s_bn = 0.0; }
    __syncthreads();

    if (active) {
        const int* labRow = (r < B_ROWS) ? (labels + (size_t)r * C_CLS)
                                         : (memL + (size_t)(r - B_ROWS) * C_CLS);
        float wfac = (r < B_ROWS) ? 2.0f : 1.0f;   // z_img rows duplicated in enhanced set
        const float4* s4 = (const float4*)(g_sim + (size_t)r * C_CLS);
        const int4*   l4 = (const int4*)labRow;

        unsigned posm = 0u;
        float t[HARD_K];
        #pragma unroll
        for (int j = 0; j < HARD_K; j++) t[j] = NEG_INF;
        float maxpos = NEG_INF;

        // pass 1: global load once -> smem cache; pos mask; per-lane sorted(desc) top-10 of negs
        #pragma unroll
        for (int i = 0; i < 8; i++) {
            int k = i * 32 + lane;
            bool okv = (k < 250);
            int kc = okv ? k : 249;               // clamp (no OOB); masked below
            float4 v4 = s4[kc];
            int4   b4 = l4[kc];
            if (okv) s_val[wid][k] = v4;          // cache only valid chunks
            if (!okv) {
                v4.x = v4.y = v4.z = v4.w = NEG_INF;
                b4.x = b4.y = b4.z = b4.w = 0;
            }
            float vv[4] = {v4.x, v4.y, v4.z, v4.w};
            int   ll[4] = {b4.x, b4.y, b4.z, b4.w};
            #pragma unroll
            for (int j = 0; j < 4; j++) {
                float v = vv[j];
                int idx = i * 4 + j;
                if (ll[j] > 0) {
                    posm |= (1u << idx);
                    maxpos = fmaxf(maxpos, v);
                } else if (v > t[HARD_K - 1]) {
                    t[HARD_K - 1] = v;
                    #pragma unroll
                    for (int q = HARD_K - 1; q > 0; q--) {
                        if (t[q] > t[q - 1]) { float tm = t[q - 1]; t[q - 1] = t[q]; t[q] = tm; }
                    }
                }
            }
        }

        // merge: exact 10th-largest negative across the warp (with multiplicity)
        float thr = NEG_INF, top1 = NEG_INF;
        for (int it = 0; it < HARD_K; it++) {
            float mx = t[0];
            #pragma unroll
            for (int o = 16; o; o >>= 1) mx = fmaxf(mx, __shfl_xor_sync(0xffffffffu, mx, o));
            if (it == 0) top1 = mx;
            if (it == HARD_K - 1) { thr = mx; break; }
            unsigned ball = __ballot_sync(0xffffffffu, t[0] == mx);
            int owner = __ffs(ball) - 1;
            if (lane == owner) {   // pop head
                #pragma unroll
                for (int j = 0; j < HARD_K - 1; j++) t[j] = t[j + 1];
                t[HARD_K - 1] = NEG_INF;
            }
        }

        float mp2 = maxpos;
        #pragma unroll
        for (int o = 16; o; o >>= 1) mp2 = fmaxf(mp2, __shfl_xor_sync(0xffffffffu, mp2, o));
        float mx = fmaxf(mp2, top1);

        // pass 2: re-read from SMEM -> masked sumexp + weighted sums
        float se = 0.0f, ws = 0.0f, wv = 0.0f;
        const float4* gw4 = (const float4*)g_w;
        #pragma unroll
        for (int i = 0; i < 8; i++) {
            int k = i * 32 + lane;
            bool okv = (k < 250);
            int kc = okv ? k : 249;
            float4 v4;
            if (okv) {
                v4 = s_val[wid][k];
            } else {
                v4.x = v4.y = v4.z = v4.w = NEG_INF;
            }
            float4 w4 = gw4[kc];                  // g_w padded to 1024 -> always safe
            float vv[4] = {v4.x, v4.y, v4.z, v4.w};
            float ww[4] = {w4.x, w4.y, w4.z, w4.w};
            #pragma unroll
            for (int j = 0; j < 4; j++) {
                int idx = i * 4 + j;
                float v = vv[j];
                bool p = (posm >> idx) & 1u;
                if (p || v >= thr) se += __expf(v - mx);
                if (p) {
                    ws += ww[j];
                    wv += ww[j] * v;
                }
            }
        }
        #pragma unroll
        for (int o = 16; o; o >>= 1) {
            se += __shfl_xor_sync(0xffffffffu, se, o);
            ws += __shfl_xor_sync(0xffffffffu, ws, o);
            wv += __shfl_xor_sync(0xffffffffu, wv, o);
        }

        if (lane == 0 && ws > 0.0f) {
            float lse = mx + logf(se);
            atomicAdd(&s_bl, (double)(wfac * ((lse * ws - wv) / (ws + EPSF))));
            atomicAdd(&s_bn, (double)wfac);
        }
    }

    __syncthreads();
    if (threadIdx.x == 0 && s_bn != 0.0) {
        atomicAdd(&g_loss, s_bl);
        atomicAdd(&g_nvalid, s_bn);
    }
}

__global__ void finalize_kernel(float* __restrict__ out) {
    double nv = g_nvalid;
    if (nv < 1.0) nv = 1.0;
    out[0] = (float)(g_loss / nv);
}

// ---------------- launch ----------------
extern "C" void kernel_launch(void* const* d_in, const int* in_sizes, int n_in,
                              void* d_out, int out_size) {
    const float* img     = (const float*)d_in[0];
    const float* prompts = (const float*)d_in[1];
    const int*   labels  = (const int*)d_in[2];
    const float* memF    = (const float*)d_in[3];
    const int*   memL    = (const int*)d_in[4];
    const int*   memptr  = (const int*)d_in[5];
    float* out = (float*)d_out;
    (void)in_sizes; (void)n_in; (void)out_size;

    cudaFuncSetAttribute(gemm_mma_kernel, cudaFuncAttributeMaxDynamicSharedMemorySize, GSM_DYN);

    stage_kernel<<<STAGE_GRID, 256>>>(img, prompts, memF, labels, memptr);
    weights_kernel<<<1, 1024>>>();
    gemm_mma_kernel<<<dim3(8, MAXR / 128), 256, GSM_DYN>>>(memptr);
    epilogue_kernel<<<(MAXR + 7) / 8, 256>>>(labels, memL, memptr);
    finalize_kernel<<<1, 1>>>(out);
}